// round 1
// baseline (speedup 1.0000x reference)
#include <cuda_runtime.h>
#include <math.h>

// Problem constants
#define B_      8
#define SEQ_    16384
#define D_      384
#define QKVD_   1152
#define H_      8
#define C_      48
#define TOK_    (B_ * SEQ_)          // 131072

// ---------------- scratch (static device globals; no allocs allowed) ----------------
__device__ float g_qkv[(size_t)TOK_ * QKVD_];      // 604 MB : x @ W_qkv
__device__ float g_attn[(size_t)TOK_ * D_];        // 201 MB : per-head attention output
__device__ float g_ctx[B_ * H_ * C_ * C_];         // unnormalized k^T v context
__device__ float g_sum[B_ * H_ * C_];              // sum of exp(k) over tokens

// ---------------- zero the atomic accumulators (graph replays!) ----------------
__global__ void zero_ctx_kernel() {
    int i = blockIdx.x * 256 + threadIdx.x;
    if (i < B_ * H_ * C_ * C_) g_ctx[i] = 0.0f;
    if (i < B_ * H_ * C_)      g_sum[i] = 0.0f;
}

// ---------------- 128x128x8 SIMT fp32 GEMM: C[M,N] = A[M,K] @ B[K,N] (+bias) ----------------
// Requires M%128==0, N%128==0, K%8==0 (true for all our shapes).
__global__ void __launch_bounds__(256)
sgemm_kernel(const float* __restrict__ A, const float* __restrict__ Bm,
             const float* __restrict__ bias, float* __restrict__ C,
             int M, int N, int K, int has_bias)
{
    __shared__ float As[8][128];
    __shared__ float Bs[8][128];

    const int tid = threadIdx.x;
    const int m0 = blockIdx.y * 128;
    const int n0 = blockIdx.x * 128;

    // A tile load mapping: 128 rows x 8 k, one float4 per thread
    const int a_row = tid >> 1;           // tid/2
    const int a_col = (tid & 1) * 4;      // 0 or 4
    // B tile load mapping: 8 k rows x 128 cols, one float4 per thread
    const int b_row = tid >> 5;           // 0..7
    const int b_col = (tid & 31) * 4;     // 0..124

    const int tx = tid & 15;              // 0..15 -> 8 output cols each
    const int ty = tid >> 4;              // 0..15 -> 8 output rows each

    float acc[8][8];
#pragma unroll
    for (int i = 0; i < 8; i++)
#pragma unroll
        for (int j = 0; j < 8; j++) acc[i][j] = 0.0f;

    for (int k0 = 0; k0 < K; k0 += 8) {
        float4 av = *(const float4*)&A[(size_t)(m0 + a_row) * K + k0 + a_col];
        float4 bv = *(const float4*)&Bm[(size_t)(k0 + b_row) * N + n0 + b_col];
        __syncthreads();
        As[a_col + 0][a_row] = av.x;
        As[a_col + 1][a_row] = av.y;
        As[a_col + 2][a_row] = av.z;
        As[a_col + 3][a_row] = av.w;
        *(float4*)&Bs[b_row][b_col] = bv;
        __syncthreads();
#pragma unroll
        for (int kk = 0; kk < 8; kk++) {
            float a[8], b[8];
            *(float4*)&a[0] = *(const float4*)&As[kk][ty * 8];
            *(float4*)&a[4] = *(const float4*)&As[kk][ty * 8 + 4];
            *(float4*)&b[0] = *(const float4*)&Bs[kk][tx * 8];
            *(float4*)&b[4] = *(const float4*)&Bs[kk][tx * 8 + 4];
#pragma unroll
            for (int i = 0; i < 8; i++)
#pragma unroll
                for (int j = 0; j < 8; j++) acc[i][j] += a[i] * b[j];
        }
    }

    float bb[8];
#pragma unroll
    for (int j = 0; j < 8; j++)
        bb[j] = has_bias ? bias[n0 + tx * 8 + j] : 0.0f;

#pragma unroll
    for (int i = 0; i < 8; i++) {
        float* cp = &C[(size_t)(m0 + ty * 8 + i) * N + n0 + tx * 8];
        float4 v0 = make_float4(acc[i][0] + bb[0], acc[i][1] + bb[1],
                                acc[i][2] + bb[2], acc[i][3] + bb[3]);
        float4 v1 = make_float4(acc[i][4] + bb[4], acc[i][5] + bb[5],
                                acc[i][6] + bb[6], acc[i][7] + bb[7]);
        *(float4*)cp = v0;
        *(float4*)(cp + 4) = v1;
    }
}

// ---------------- context: ctx[b,h,c,d] += sum_n exp(k[n,c]) * v[n,d]; sum[c] += sum_n exp(k[n,c]) ----------------
// grid (NSPLIT=128, H, B), block (48, 6). Each block does 128 token rows.
#define NSPLIT_ 128
#define CROWS_  (SEQ_ / NSPLIT_)   // 128

__global__ void __launch_bounds__(288)
ctx_kernel()
{
    const int c = threadIdx.x;                 // 0..47
    const int g = threadIdx.y;                 // 0..5
    const int tid = g * 48 + c;                // 0..287
    const int split = blockIdx.x;
    const int h = blockIdx.y;
    const int b = blockIdx.z;
    const int n0 = split * CROWS_;
    const float* base = g_qkv + (size_t)(b * SEQ_ + n0) * QKVD_ + h * C_;

    __shared__ float ek[32][48];
    __shared__ float vs[32][48];

    float acc[8];
#pragma unroll
    for (int j = 0; j < 8; j++) acc[j] = 0.0f;
    float ssum = 0.0f;
    const int d0 = g * 8;

    for (int r0 = 0; r0 < CROWS_; r0 += 32) {
        __syncthreads();
        for (int idx = tid; idx < 32 * 48; idx += 288) {
            int r = idx / 48, cc = idx % 48;
            const float* rowp = base + (size_t)(r0 + r) * QKVD_ + cc;
            ek[r][cc] = __expf(rowp[384]);   // k block at cols 384..767
            vs[r][cc] = rowp[768];           // v block at cols 768..1151
        }
        __syncthreads();
#pragma unroll 4
        for (int r = 0; r < 32; r++) {
            float e = ek[r][c];
            if (g == 0) ssum += e;
#pragma unroll
            for (int j = 0; j < 8; j++) acc[j] += e * vs[r][d0 + j];
        }
    }

    float* cp = g_ctx + (((size_t)(b * H_ + h)) * C_ + c) * C_ + d0;
#pragma unroll
    for (int j = 0; j < 8; j++) atomicAdd(&cp[j], acc[j]);
    if (g == 0) atomicAdd(&g_sum[(b * H_ + h) * C_ + c], ssum);
}

// ---------------- attn: out[t, h*48+d] = sum_c softmax_c(q[t,h,:])[c] * ctxn[c,d] ----------------
// grid (SEQ/128, H, B), block 256. Normalized context cached in smem.
#define TB_ 128

__global__ void __launch_bounds__(256)
attn_kernel()
{
    const int tb = blockIdx.x;
    const int h  = blockIdx.y;
    const int b  = blockIdx.z;
    const int tid = threadIdx.x;

    __shared__ float ctxn[48][48];
    __shared__ float eq[16][48];
    __shared__ float srow[16];
    __shared__ float sinv[48];

    if (tid < 48) sinv[tid] = 1.0f / g_sum[(b * H_ + h) * C_ + tid];
    __syncthreads();
    for (int idx = tid; idx < 48 * 48; idx += 256) {
        int c = idx / 48, d = idx % 48;
        ctxn[c][d] = g_ctx[(((size_t)(b * H_ + h)) * C_ + c) * C_ + d] * sinv[c];
    }

    const int n0 = tb * TB_;
    const float* qbase = g_qkv + (size_t)(b * SEQ_ + n0) * QKVD_ + h * C_;  // q at cols 0..383
    float* obase = g_attn + (size_t)(b * SEQ_ + n0) * D_ + h * C_;

    for (int r0 = 0; r0 < TB_; r0 += 16) {
        __syncthreads();
        for (int idx = tid; idx < 16 * 48; idx += 256) {
            int r = idx / 48, c = idx % 48;
            eq[r][c] = __expf(qbase[(size_t)(r0 + r) * QKVD_ + c]);
        }
        __syncthreads();
        if (tid < 16) {
            float s = 0.0f;
#pragma unroll
            for (int c = 0; c < 48; c++) s += eq[tid][c];
            srow[tid] = 1.0f / s;
        }
        __syncthreads();
        for (int idx = tid; idx < 16 * 48; idx += 256) {
            int r = idx / 48, d = idx % 48;
            float a = 0.0f;
#pragma unroll
            for (int c = 0; c < 48; c++) a += eq[r][c] * ctxn[c][d];
            obase[(size_t)(r0 + r) * D_ + d] = a * srow[r];
        }
    }
}

// ---------------- launch ----------------
extern "C" void kernel_launch(void* const* d_in, const int* in_sizes, int n_in,
                              void* d_out, int out_size)
{
    const float* x     = (const float*)d_in[0];
    const float* Wqkv  = (const float*)d_in[1];
    const float* Wproj = (const float*)d_in[2];
    const float* bproj = (const float*)d_in[3];
    float* out = (float*)d_out;

    float *p_qkv, *p_attn;
    cudaGetSymbolAddress((void**)&p_qkv, g_qkv);
    cudaGetSymbolAddress((void**)&p_attn, g_attn);

    // 1) zero atomic accumulators
    zero_ctx_kernel<<<(B_ * H_ * C_ * C_ + 255) / 256, 256>>>();

    // 2) qkv = x @ W_qkv   [131072 x 384] @ [384 x 1152]
    {
        dim3 grid(QKVD_ / 128, TOK_ / 128);
        sgemm_kernel<<<grid, 256>>>(x, Wqkv, nullptr, p_qkv, TOK_, QKVD_, D_, 0);
    }

    // 3) context reduction over tokens
    {
        dim3 grid(NSPLIT_, H_, B_);
        dim3 blk(48, 6);
        ctx_kernel<<<grid, blk>>>();
    }

    // 4) q-softmax @ context
    {
        dim3 grid(SEQ_ / TB_, H_, B_);
        attn_kernel<<<grid, 256>>>();
    }

    // 5) out = attn @ W_proj + b_proj   [131072 x 384] @ [384 x 384]
    {
        dim3 grid(D_ / 128, TOK_ / 128);
        sgemm_kernel<<<grid, 256>>>(p_attn, Wproj, bproj, out, TOK_, D_, D_, 1);
    }
}

// round 3
// speedup vs baseline: 2.1909x; 2.1909x over previous
#include <cuda_runtime.h>
#include <math.h>
#include <stdint.h>

// Problem constants
#define B_      8
#define SEQ_    16384
#define D_      384
#define QKVD_   1152
#define H_      8
#define C_      48
#define TOK_    (B_ * SEQ_)          // 131072

// ---------------- scratch (static device globals; no allocs allowed) ----------------
__device__ float g_qkv[(size_t)TOK_ * QKVD_];      // 604 MB : x @ W_qkv
__device__ float g_attn[(size_t)TOK_ * D_];        // 201 MB : per-head attention output
__device__ float g_ctx[B_ * H_ * C_ * C_];         // unnormalized k^T v context
__device__ float g_sum[B_ * H_ * C_];              // sum of exp(k) over tokens
__device__ float g_Wtq[QKVD_ * D_];                // W_qkv transposed: [1152][384]
__device__ float g_Wtp[D_ * D_];                   // W_proj transposed: [384][384]

// ---------------- zero the atomic accumulators (graph replays!) ----------------
__global__ void zero_ctx_kernel() {
    int i = blockIdx.x * 256 + threadIdx.x;
    if (i < B_ * H_ * C_ * C_) g_ctx[i] = 0.0f;
    if (i < B_ * H_ * C_)      g_sum[i] = 0.0f;
}

// ---------------- weight transpose: src[R][Ccols] -> dst[Ccols][R] ----------------
__global__ void transpose_kernel(const float* __restrict__ src, float* __restrict__ dst,
                                 int R, int Ccols) {
    __shared__ float t[32][33];
    int bx = blockIdx.x * 32, by = blockIdx.y * 32;
    int tx = threadIdx.x, ty = threadIdx.y;
#pragma unroll
    for (int j = 0; j < 32; j += 8)
        t[ty + j][tx] = src[(size_t)(by + ty + j) * Ccols + bx + tx];
    __syncthreads();
#pragma unroll
    for (int j = 0; j < 32; j += 8)
        dst[(size_t)(bx + ty + j) * R + by + tx] = t[tx][ty + j];
}

// ================= tf32 mma.sync GEMM =================
// C[M,N] = A[M,K] @ Bt[N,K]^T (+bias).  A row-major, Bt row-major (K contiguous).
// Block tile 128x128, BK=32, 4 warps (2x2), warp tile 64x64.
// m16n8k8 tf32 HMMA; cp.async double-buffered smem; pad-36 rows -> conflict-free LDS.

#define BM_ 128
#define BN_ 128
#define BK_ 32
#define PADS_ 36                    // floats per smem row
#define GSM_BYTES (4 * (2 * BM_ * PADS_ + 2 * BN_ * PADS_) * 4 / 4)  // see below

__device__ __forceinline__ uint32_t smem_u32(const void* p) {
    uint32_t a;
    asm("{ .reg .u64 t; cvta.to.shared.u64 t, %1; cvt.u32.u64 %0, t; }" : "=r"(a) : "l"(p));
    return a;
}
__device__ __forceinline__ void cp_async16(uint32_t dst, const void* src) {
    asm volatile("cp.async.cg.shared.global [%0], [%1], 16;" :: "r"(dst), "l"(src));
}
__device__ __forceinline__ uint32_t f2tf32u(float x) {
    uint32_t y;
    asm("cvt.rna.tf32.f32 %0, %1;" : "=r"(y) : "f"(x));
    return y;
}
__device__ __forceinline__ void mma_tf32(float* c, const uint32_t* a, const uint32_t* b) {
    asm volatile(
        "mma.sync.aligned.m16n8k8.row.col.f32.tf32.tf32.f32 "
        "{%0,%1,%2,%3}, {%4,%5,%6,%7}, {%8,%9}, {%0,%1,%2,%3};"
        : "+f"(c[0]), "+f"(c[1]), "+f"(c[2]), "+f"(c[3])
        : "r"(a[0]), "r"(a[1]), "r"(a[2]), "r"(a[3]), "r"(b[0]), "r"(b[1]));
}

__global__ void __launch_bounds__(128, 2)
gemm_mma(const float* __restrict__ A, const float* __restrict__ Bt,
         const float* __restrict__ bias, float* __restrict__ Cm,
         int M, int N, int K, int has_bias)
{
    extern __shared__ float smem[];
    float* As = smem;                          // 2 * 128 * 36
    float* Bs = smem + 2 * BM_ * PADS_;        // 2 * 128 * 36

    const int tid = threadIdx.x;
    const int wid = tid >> 5;
    const int lane = tid & 31;
    const int m0 = blockIdx.y * BM_;
    const int n0 = blockIdx.x * BN_;
    const int wm = (wid & 1) * 64;
    const int wn = (wid >> 1) * 64;

    const int lr = lane >> 2;   // 0..7
    const int lc = lane & 3;    // 0..3

    // cp.async mapping: 128 rows x 8 float4/row; thread -> rows (tid/8)+16i, float4 (tid&7)
    const int gr = tid >> 3;          // 0..15
    const int gc = (tid & 7) * 4;     // float offset

    const uint32_t as_base = smem_u32(As);
    const uint32_t bs_base = smem_u32(Bs);

    float acc[4][8][4];
#pragma unroll
    for (int i = 0; i < 4; i++)
#pragma unroll
        for (int j = 0; j < 8; j++)
#pragma unroll
            for (int r = 0; r < 4; r++) acc[i][j][r] = 0.0f;

    const int nch = K / BK_;

    // ---- load chunk 0 ----
    {
        const int k0 = 0;
#pragma unroll
        for (int i = 0; i < 8; i++) {
            int row = gr + i * 16;
            cp_async16(as_base + (row * PADS_ + gc) * 4, &A[(size_t)(m0 + row) * K + k0 + gc]);
            cp_async16(bs_base + (row * PADS_ + gc) * 4, &Bt[(size_t)(n0 + row) * K + k0 + gc]);
        }
        asm volatile("cp.async.commit_group;");
    }

    for (int c = 0; c < nch; c++) {
        asm volatile("cp.async.wait_group 0;");
        __syncthreads();

        if (c + 1 < nch) {
            const int k0 = (c + 1) * BK_;
            const int buf = (c + 1) & 1;
            const uint32_t ab = as_base + buf * BM_ * PADS_ * 4;
            const uint32_t bb = bs_base + buf * BN_ * PADS_ * 4;
#pragma unroll
            for (int i = 0; i < 8; i++) {
                int row = gr + i * 16;
                cp_async16(ab + (row * PADS_ + gc) * 4, &A[(size_t)(m0 + row) * K + k0 + gc]);
                cp_async16(bb + (row * PADS_ + gc) * 4, &Bt[(size_t)(n0 + row) * K + k0 + gc]);
            }
            asm volatile("cp.async.commit_group;");
        }

        const float* as = As + (c & 1) * BM_ * PADS_;
        const float* bs = Bs + (c & 1) * BN_ * PADS_;

#pragma unroll
        for (int ks = 0; ks < 4; ks++) {
            const int kk = ks * 8 + lc;
            uint32_t afr[4][4];
#pragma unroll
            for (int mi = 0; mi < 4; mi++) {
                int r = wm + mi * 16 + lr;
                afr[mi][0] = f2tf32u(as[r * PADS_ + kk]);
                afr[mi][1] = f2tf32u(as[(r + 8) * PADS_ + kk]);
                afr[mi][2] = f2tf32u(as[r * PADS_ + kk + 4]);
                afr[mi][3] = f2tf32u(as[(r + 8) * PADS_ + kk + 4]);
            }
            uint32_t bfr[8][2];
#pragma unroll
            for (int nj = 0; nj < 8; nj++) {
                int nn = wn + nj * 8 + lr;
                bfr[nj][0] = f2tf32u(bs[nn * PADS_ + kk]);
                bfr[nj][1] = f2tf32u(bs[nn * PADS_ + kk + 4]);
            }
#pragma unroll
            for (int mi = 0; mi < 4; mi++)
#pragma unroll
                for (int nj = 0; nj < 8; nj++)
                    mma_tf32(acc[mi][nj], afr[mi], bfr[nj]);
        }
        __syncthreads();
    }

    // ---- epilogue ----
#pragma unroll
    for (int mi = 0; mi < 4; mi++) {
        const int r0 = m0 + wm + mi * 16 + lr;
#pragma unroll
        for (int nj = 0; nj < 8; nj++) {
            const int col = n0 + wn + nj * 8 + lc * 2;
            float2 b2 = make_float2(0.f, 0.f);
            if (has_bias) b2 = *(const float2*)&bias[col];
            float2 v0 = make_float2(acc[mi][nj][0] + b2.x, acc[mi][nj][1] + b2.y);
            float2 v1 = make_float2(acc[mi][nj][2] + b2.x, acc[mi][nj][3] + b2.y);
            *(float2*)&Cm[(size_t)r0 * N + col] = v0;
            *(float2*)&Cm[(size_t)(r0 + 8) * N + col] = v1;
        }
    }
}

// ---------------- context: ctx[b,h,c,d] += sum_n exp(k[n,c]) * v[n,d]; sum[c] += sum_n exp(k[n,c]) ----------------
#define NSPLIT_ 128
#define CROWS_  (SEQ_ / NSPLIT_)   // 128

__global__ void __launch_bounds__(288)
ctx_kernel()
{
    const int c = threadIdx.x;                 // 0..47
    const int g = threadIdx.y;                 // 0..5
    const int tid = g * 48 + c;                // 0..287
    const int split = blockIdx.x;
    const int h = blockIdx.y;
    const int b = blockIdx.z;
    const int n0 = split * CROWS_;
    const float* base = g_qkv + (size_t)(b * SEQ_ + n0) * QKVD_ + h * C_;

    __shared__ float ek[32][48];
    __shared__ float vs[32][48];

    float4 acc0 = make_float4(0.f, 0.f, 0.f, 0.f);
    float4 acc1 = make_float4(0.f, 0.f, 0.f, 0.f);
    float ssum = 0.0f;
    const int d0 = g * 8;

    for (int r0 = 0; r0 < CROWS_; r0 += 32) {
        __syncthreads();
        for (int idx = tid; idx < 32 * 48; idx += 288) {
            int r = idx / 48, cc = idx % 48;
            const float* rowp = base + (size_t)(r0 + r) * QKVD_ + cc;
            ek[r][cc] = __expf(rowp[384]);   // k block at cols 384..767
            vs[r][cc] = rowp[768];           // v block at cols 768..1151
        }
        __syncthreads();
#pragma unroll 4
        for (int r = 0; r < 32; r++) {
            float e = ek[r][c];
            if (g == 0) ssum += e;
            float4 v0 = *(const float4*)&vs[r][d0];
            float4 v1 = *(const float4*)&vs[r][d0 + 4];
            acc0.x += e * v0.x; acc0.y += e * v0.y; acc0.z += e * v0.z; acc0.w += e * v0.w;
            acc1.x += e * v1.x; acc1.y += e * v1.y; acc1.z += e * v1.z; acc1.w += e * v1.w;
        }
    }

    float* cp = g_ctx + (((size_t)(b * H_ + h)) * C_ + c) * C_ + d0;
    atomicAdd(&cp[0], acc0.x); atomicAdd(&cp[1], acc0.y);
    atomicAdd(&cp[2], acc0.z); atomicAdd(&cp[3], acc0.w);
    atomicAdd(&cp[4], acc1.x); atomicAdd(&cp[5], acc1.y);
    atomicAdd(&cp[6], acc1.z); atomicAdd(&cp[7], acc1.w);
    if (g == 0) atomicAdd(&g_sum[(b * H_ + h) * C_ + c], ssum);
}

// ---------------- attn: out[t, h*48+d] = softmax_c(q[t,h,:]) @ ctxn ----------------
#define TB_ 128

__global__ void __launch_bounds__(192)
attn_kernel()
{
    const int tb = blockIdx.x;
    const int h  = blockIdx.y;
    const int b  = blockIdx.z;
    const int tid = threadIdx.x;

    __shared__ float ctxn[48][48];
    __shared__ float eq[16][48];
    __shared__ float srow[16];
    __shared__ float sinv[48];

    if (tid < 48) sinv[tid] = 1.0f / g_sum[(b * H_ + h) * C_ + tid];
    __syncthreads();
    for (int idx = tid; idx < 48 * 48; idx += 192) {
        int c = idx / 48, d = idx % 48;
        ctxn[c][d] = g_ctx[(((size_t)(b * H_ + h)) * C_ + c) * C_ + d] * sinv[c];
    }

    const int n0 = tb * TB_;
    const float* qbase = g_qkv + (size_t)(b * SEQ_ + n0) * QKVD_ + h * C_;  // q at cols 0..383
    float* obase = g_attn + (size_t)(b * SEQ_ + n0) * D_ + h * C_;

    const int rr = tid / 12;        // 0..15
    const int dg = tid % 12;        // 0..11 -> cols dg*4..dg*4+3

    for (int r0 = 0; r0 < TB_; r0 += 16) {
        __syncthreads();
        for (int idx = tid; idx < 16 * 48; idx += 192) {
            int r = idx / 48, c = idx % 48;
            eq[r][c] = __expf(qbase[(size_t)(r0 + r) * QKVD_ + c]);
        }
        __syncthreads();
        if (tid < 16) {
            float s = 0.0f;
#pragma unroll
            for (int c = 0; c < 48; c++) s += eq[tid][c];
            srow[tid] = 1.0f / s;
        }
        __syncthreads();
        {
            float4 acc = make_float4(0.f, 0.f, 0.f, 0.f);
#pragma unroll
            for (int c = 0; c < 48; c++) {
                float e = eq[rr][c];
                float4 cv = *(const float4*)&ctxn[c][dg * 4];
                acc.x += e * cv.x; acc.y += e * cv.y; acc.z += e * cv.z; acc.w += e * cv.w;
            }
            float s = srow[rr];
            acc.x *= s; acc.y *= s; acc.z *= s; acc.w *= s;
            *(float4*)&obase[(size_t)(r0 + rr) * D_ + dg * 4] = acc;
        }
    }
}

// ---------------- launch ----------------
extern "C" void kernel_launch(void* const* d_in, const int* in_sizes, int n_in,
                              void* d_out, int out_size)
{
    const float* x     = (const float*)d_in[0];
    const float* Wqkv  = (const float*)d_in[1];
    const float* Wproj = (const float*)d_in[2];
    const float* bproj = (const float*)d_in[3];
    float* out = (float*)d_out;

    float *p_qkv, *p_attn, *p_wtq, *p_wtp;
    cudaGetSymbolAddress((void**)&p_qkv, g_qkv);
    cudaGetSymbolAddress((void**)&p_attn, g_attn);
    cudaGetSymbolAddress((void**)&p_wtq, g_Wtq);
    cudaGetSymbolAddress((void**)&p_wtp, g_Wtp);

    const int smem_bytes = (2 * BM_ * PADS_ + 2 * BN_ * PADS_) * 4;  // 73728
    cudaFuncSetAttribute(gemm_mma, cudaFuncAttributeMaxDynamicSharedMemorySize, smem_bytes);

    // 0) transpose weights to K-major
    transpose_kernel<<<dim3(QKVD_ / 32, D_ / 32), dim3(32, 8)>>>(Wqkv, p_wtq, D_, QKVD_);
    transpose_kernel<<<dim3(D_ / 32, D_ / 32), dim3(32, 8)>>>(Wproj, p_wtp, D_, D_);

    // 1) zero atomic accumulators
    zero_ctx_kernel<<<(B_ * H_ * C_ * C_ + 255) / 256, 256>>>();

    // 2) qkv = x @ W_qkv   [131072 x 384] @ [384 x 1152]
    {
        dim3 grid(QKVD_ / BN_, TOK_ / BM_);
        gemm_mma<<<grid, 128, smem_bytes>>>(x, p_wtq, nullptr, p_qkv, TOK_, QKVD_, D_, 0);
    }

    // 3) context reduction over tokens
    {
        dim3 grid(NSPLIT_, H_, B_);
        dim3 blk(48, 6);
        ctx_kernel<<<grid, blk>>>();
    }

    // 4) q-softmax @ context
    {
        dim3 grid(SEQ_ / TB_, H_, B_);
        attn_kernel<<<grid, 192>>>();
    }

    // 5) out = attn @ W_proj + b_proj   [131072 x 384] @ [384 x 384]
    {
        dim3 grid(D_ / BN_, TOK_ / BM_);
        gemm_mma<<<grid, 128, smem_bytes>>>(p_attn, p_wtp, bproj, out, TOK_, D_, D_, 1);
    }
}